// round 15
// baseline (speedup 1.0000x reference)
#include <cuda_runtime.h>
#include <cuda_fp16.h>
#include <math.h>
#include <stdint.h>

#define TWO_PI_F   6.283185307179586f
#define INV_TWO_PI 0.15915494309189535f
#define NT    12
#define KMIX  16
#define HDIM  256
#define LLEN  3072
#define BATCH 64
#define EPSF  1e-6f
#define MCTA  128
#define GRID  512
#define THREADS 512

#define APITCH   528
#define APLANE   67584
#define OFF_A    0
#define B2PLANE  16896
#define OFF_B2_0 135168
#define OFF_B2_1 168960
#define B3PITCH  144
#define B3PLANE  36864
#define OFF_B3   135168
#define OFF_PB   0
#define OFF_C1   208896
#define OFF_C2   209408
#define OFF_B2S  209920
#define OFF_B3S  210944
#define OFF_LDJP 211200
#define SMEM_DYN 211456

__device__ float g_z[BATCH * LLEN];
__device__ float g_part[NT * GRID];
__device__ uint32_t g_flag[NT][GRID];
__device__ __align__(16) __half g_w2hi[NT * 256 * 256];
__device__ __align__(16) __half g_w2lo[NT * 256 * 256];
__device__ __align__(16) __half g_w3hi[NT * 256 * 64];
__device__ __align__(16) __half g_w3lo[NT * 256 * 64];

__device__ __forceinline__ float mod2pi(float x) {
    float r = fmodf(x, TWO_PI_F);
    return (r < 0.f) ? r + TWO_PI_F : r;
}
__device__ __forceinline__ float tanh_fast(float x) {
    float y; asm("tanh.approx.f32 %0, %1;" : "=f"(y) : "f"(x)); return y;
}
__device__ __forceinline__ uint32_t smem_u32(const void* p) {
    uint32_t a;
    asm("{ .reg .u64 t; cvta.to.shared.u64 t, %1; cvt.u32.u64 %0, t; }" : "=r"(a) : "l"(p));
    return a;
}
__device__ __forceinline__ uint32_t pack2h(float a, float b) {
    __half2 h = __floats2half2_rn(a, b);
    return *(uint32_t*)&h;
}

#define MMA(C, A, B0, B1) \
    asm volatile("mma.sync.aligned.m16n8k16.row.col.f32.f16.f16.f32 " \
        "{%0,%1,%2,%3},{%4,%5,%6,%7},{%8,%9},{%0,%1,%2,%3};" \
        : "+f"((C)[0]), "+f"((C)[1]), "+f"((C)[2]), "+f"((C)[3]) \
        : "r"((A)[0]), "r"((A)[1]), "r"((A)[2]), "r"((A)[3]), "r"(B0), "r"(B1))
#define LDSM4(R, a) \
    asm volatile("ldmatrix.sync.aligned.m8n8.x4.shared.b16 {%0,%1,%2,%3}, [%4];" \
        : "=r"((R)[0]), "=r"((R)[1]), "=r"((R)[2]), "=r"((R)[3]) : "r"(a))
#define LDSM4T(R, a) \
    asm volatile("ldmatrix.sync.aligned.m8n8.x4.trans.shared.b16 {%0,%1,%2,%3}, [%4];" \
        : "=r"((R)[0]), "=r"((R)[1]), "=r"((R)[2]), "=r"((R)[3]) : "r"(a))
#define CPASYNC16(d, s) asm volatile("cp.async.ca.shared.global [%0], [%1], 16;" :: "r"(d), "l"(s))
#define CPCOMMIT()      asm volatile("cp.async.commit_group;" ::: "memory")
#define CPWAIT0()       asm volatile("cp.async.wait_group 0;" ::: "memory")

__global__ void prep_w2(const float* __restrict__ W2) {
    int i = blockIdx.x * blockDim.x + threadIdx.x;
    if (i >= NT * 256 * 256) return;
    float v = W2[i];
    __half hi = __float2half_rn(v);
    g_w2hi[i] = hi;
    g_w2lo[i] = __float2half_rn(v - __half2float(hi));
}
__global__ void prep_w3(const float* __restrict__ W3) {
    int i = blockIdx.x * blockDim.x + threadIdx.x;
    if (i >= NT * 256 * 64) return;
    int n = i & 63, k = (i >> 6) & 255, t = i >> 14;
    float v = (n < 48) ? W3[((size_t)t * 256 + k) * 48 + n] : 0.f;
    __half hi = __float2half_rn(v);
    g_w3hi[i] = hi;
    g_w3lo[i] = __float2half_rn(v - __half2float(hi));
}
__global__ void init_kernel(const float* __restrict__ z_in) {
    int i = blockIdx.x * blockDim.x + threadIdx.x;
    if (i < BATCH * LLEN) g_z[i] = z_in[i];
    if (i < NT * GRID) ((uint32_t*)g_flag)[i] = 0u;
}

__global__ __launch_bounds__(THREADS, 1)
void step_kernel(const float* __restrict__ W1, const float* __restrict__ b1,
                 const float* __restrict__ b2, const float* __restrict__ b3,
                 int t, int off)
{
    cudaTriggerProgrammaticLaunchCompletion();

    extern __shared__ __align__(16) char dsm[];
    const uint32_t base = smem_u32(dsm);
    char* gb = dsm;

    const int tid  = threadIdx.x;
    const int lane = tid & 31;
    const int wp   = tid >> 5;
    const int mh   = wp >> 3;
    const int ns   = wp & 7;
    const int blk  = blockIdx.x;
    const int bat  = blk >> 3;
    const int chnk = blk & 7;

    const float* W1t = W1 + t * 2 * HDIM;
    const float* b1t = b1 + t * HDIM;
    const float* zrow = g_z + bat * LLEN;

    // ---- z-independent prologue: biases + B2 chunk 0 prefetch ----
    if (tid < 64) {
        *(float4*)(gb + OFF_B2S + tid * 16) = __ldg((const float4*)&b2[t * 256 + tid * 4]);
    } else if (tid < 76) {
        *(float4*)(gb + OFF_B3S + (tid - 64) * 16) = __ldg((const float4*)&b3[t * 48 + (tid - 64) * 4]);
    }
    for (int i = tid; i < 2048; i += THREADS) {
        int p = i >> 10, r = (i >> 5) & 31, seg = i & 31;
        const __half* src = (p ? g_w2lo : g_w2hi) + ((size_t)(t * 256 + r) * 256 + seg * 8);
        CPASYNC16(base + OFF_B2_0 + p * B2PLANE + r * APITCH + seg * 16, src);
    }
    CPCOMMIT();

    // ---- wait for producer chunks of previous step (c-1, c, c+1) ----
    if (t > 0) {
        if (tid < 3) {
            int nb = (chnk + tid + 7) & 7;
            volatile uint32_t* f = &g_flag[t - 1][bat * 8 + nb];
            while (*f == 0u) { }
        }
        __threadfence();
    }
    __syncthreads();

    // ---- phase 0: per-site context ----
    float sv = 0.f, dsdu = 0.f, lgt = 0.f, zr = 0.f;
    if (tid < MCTA) {
        int idx = 3 * (chnk * MCTA + tid) + off;
        int im2 = idx - 2; if (im2 < 0) im2 += LLEN;
        int im1 = idx - 1; if (im1 < 0) im1 += LLEN;
        int ip1 = idx + 1; if (ip1 >= LLEN) ip1 -= LLEN;
        int ip2 = idx + 2; if (ip2 >= LLEN) ip2 -= LLEN;
        float zm2 = zrow[im2], zm1 = zrow[im1], z0 = zrow[idx];
        float zp1 = zrow[ip1], zp2 = zrow[ip2];
        *(float*)(gb + OFF_C1 + tid * 4) = mod2pi(zm1 - zm2);
        *(float*)(gb + OFF_C2 + tid * 4) = mod2pi(zp2 - zp1);
        float Vc = mod2pi(z0 - zm1);
        float u = fminf(fmaxf(Vc * INV_TWO_PI, EPSF), 1.f - EPSF);
        float a = u * u, bb = (1.f - u) * (1.f - u);
        float den = a + bb;
        sv = a / den;
        dsdu = 2.f * u * (1.f - u) / (den * den);
        sv = fminf(fmaxf(sv, EPSF), 1.f - EPSF);
        lgt = logf(sv) - log1pf(-sv);
        zr = zm1;
    }
    __syncthreads();

    // ---- layer 1: h1 -> A tile (fp16 hi + lo planes) ----
    {
        const int p = tid & 127, sh = tid >> 7;
        float w00 = __ldg(&W1t[2 * p]),       w01 = __ldg(&W1t[2 * p + 1]);
        float w10 = __ldg(&W1t[256 + 2 * p]), w11 = __ldg(&W1t[256 + 2 * p + 1]);
        float bb0 = __ldg(&b1t[2 * p]),       bb1 = __ldg(&b1t[2 * p + 1]);
        for (int s = sh * 32; s < sh * 32 + 32; s++) {
            float c1 = *(const float*)(gb + OFF_C1 + s * 4);
            float c2 = *(const float*)(gb + OFF_C2 + s * 4);
            float x0 = tanh_fast(fmaf(c1, w00, fmaf(c2, w10, bb0)));
            float x1 = tanh_fast(fmaf(c1, w01, fmaf(c2, w11, bb1)));
            __half h0 = __float2half_rn(x0), h1v = __float2half_rn(x1);
            float l0 = x0 - __half2float(h0), l1 = x1 - __half2float(h1v);
            *(uint32_t*)(gb + OFF_A + s * APITCH + 4 * p)          = pack2h(x0, x1);
            *(uint32_t*)(gb + OFF_A + APLANE + s * APITCH + 4 * p) = pack2h(l0, l1);
        }
    }
    CPWAIT0();
    __syncthreads();

    const int lr8   = ((lane >> 3) & 1) * 8 + (lane & 7);
    const int chalf = lane >> 4;

    // ---- GEMM2 ----
    float cacc[16][4];
    #pragma unroll
    for (int i = 0; i < 16; i++) { cacc[i][0]=0.f; cacc[i][1]=0.f; cacc[i][2]=0.f; cacc[i][3]=0.f; }

    const uint32_t aB2 = base + OFF_A + (mh * 64 + lr8) * APITCH + chalf * 16;

    #pragma unroll 1
    for (int c = 0; c < 8; c++) {
        const uint32_t bufc = (c & 1) ? (base + OFF_B2_1) : (base + OFF_B2_0);
        if (c < 7) {
            const uint32_t bufn = ((c + 1) & 1) ? (base + OFF_B2_1) : (base + OFF_B2_0);
            for (int i = tid; i < 2048; i += THREADS) {
                int p = i >> 10, r = (i >> 5) & 31, seg = i & 31;
                const __half* src = (p ? g_w2lo : g_w2hi) +
                    ((size_t)(t * 256 + (c + 1) * 32 + r) * 256 + seg * 8);
                CPASYNC16(bufn + p * B2PLANE + r * APITCH + seg * 16, src);
            }
            CPCOMMIT();
        }
        #pragma unroll
        for (int s = 0; s < 2; s++) {
            const int k = c * 32 + s * 16;
            uint32_t ah[4][4], al[4][4];
            #pragma unroll
            for (int mt = 0; mt < 4; mt++) {
                LDSM4(ah[mt], aB2 + mt * 16 * APITCH + k * 2);
                LDSM4(al[mt], aB2 + APLANE + mt * 16 * APITCH + k * 2);
            }
            const uint32_t brow = bufc + (s * 16 + lr8) * APITCH + ns * 64 + chalf * 16;
            #pragma unroll
            for (int nt = 0; nt < 2; nt++) {
                uint32_t bh[4], bl[4];
                LDSM4T(bh, brow + nt * 32);
                LDSM4T(bl, brow + nt * 32 + B2PLANE);
                #pragma unroll
                for (int mt = 0; mt < 4; mt++) {
                    MMA(cacc[mt * 4 + nt * 2],     ah[mt], bh[0], bh[1]);
                    MMA(cacc[mt * 4 + nt * 2 + 1], ah[mt], bh[2], bh[3]);
                    MMA(cacc[mt * 4 + nt * 2],     ah[mt], bl[0], bl[1]);
                    MMA(cacc[mt * 4 + nt * 2 + 1], ah[mt], bl[2], bl[3]);
                    MMA(cacc[mt * 4 + nt * 2],     al[mt], bh[0], bh[1]);
                    MMA(cacc[mt * 4 + nt * 2 + 1], al[mt], bh[2], bh[3]);
                }
            }
        }
        CPWAIT0();
        __syncthreads();
    }

    // ---- prefetch B3 (hi+lo), overlaying B2 buffers ----
    for (int i = tid; i < 4096; i += THREADS) {
        int p = i >> 11, r = (i >> 3) & 255, seg = i & 7;
        const __half* src = (p ? g_w3lo : g_w3hi) + ((size_t)(t * 256 + r) * 64 + seg * 8);
        CPASYNC16(base + OFF_B3 + p * B3PLANE + r * B3PITCH + seg * 16, src);
    }
    CPCOMMIT();

    // ---- convert C2 -> h2 (fp16 hi+lo) ----
    {
        #pragma unroll
        for (int mt = 0; mt < 4; mt++) {
            const int rowA = mh * 64 + mt * 16 + (lane >> 2);
            #pragma unroll
            for (int q = 0; q < 4; q++) {
                const int col = ns * 32 + q * 8 + (lane & 3) * 2;
                float2 bb = *(const float2*)(gb + OFF_B2S + col * 4);
                float x0 = tanh_fast(cacc[mt * 4 + q][0] + bb.x);
                float x1 = tanh_fast(cacc[mt * 4 + q][1] + bb.y);
                float x2 = tanh_fast(cacc[mt * 4 + q][2] + bb.x);
                float x3 = tanh_fast(cacc[mt * 4 + q][3] + bb.y);
                __half q0 = __float2half_rn(x0), q1 = __float2half_rn(x1);
                __half q2 = __float2half_rn(x2), q3 = __float2half_rn(x3);
                *(uint32_t*)(gb + OFF_A + rowA * APITCH + col * 2)       = pack2h(x0, x1);
                *(uint32_t*)(gb + OFF_A + (rowA + 8) * APITCH + col * 2) = pack2h(x2, x3);
                *(uint32_t*)(gb + OFF_A + APLANE + rowA * APITCH + col * 2) =
                    pack2h(x0 - __half2float(q0), x1 - __half2float(q1));
                *(uint32_t*)(gb + OFF_A + APLANE + (rowA + 8) * APITCH + col * 2) =
                    pack2h(x2 - __half2float(q2), x3 - __half2float(q3));
            }
        }
    }
    CPWAIT0();
    __syncthreads();

    // ---- GEMM3: 48 real columns only (np < 3; cols 48..63 are zero weights) ----
    float c3a[6][4];
    #pragma unroll
    for (int i = 0; i < 6; i++) { c3a[i][0]=0.f; c3a[i][1]=0.f; c3a[i][2]=0.f; c3a[i][3]=0.f; }
    const uint32_t aB3 = base + OFF_A + (ns * 16 + lr8) * APITCH + chalf * 16;
    #pragma unroll
    for (int j = 0; j < 8; j++) {
        const int k = mh * 128 + j * 16;
        uint32_t a3h[4], a3l[4];
        LDSM4(a3h, aB3 + k * 2);
        LDSM4(a3l, aB3 + APLANE + k * 2);
        const uint32_t b3row = base + OFF_B3 + (k + lr8) * B3PITCH + chalf * 16;
        #pragma unroll
        for (int np = 0; np < 3; np++) {
            uint32_t bh[4], bl[4];
            LDSM4T(bh, b3row + np * 32);
            LDSM4T(bl, b3row + np * 32 + B3PLANE);
            MMA(c3a[2 * np],     a3h, bh[0], bh[1]);
            MMA(c3a[2 * np + 1], a3h, bh[2], bh[3]);
            MMA(c3a[2 * np],     a3h, bl[0], bl[1]);
            MMA(c3a[2 * np + 1], a3h, bl[2], bl[3]);
            MMA(c3a[2 * np],     a3l, bh[0], bh[1]);
            MMA(c3a[2 * np + 1], a3l, bh[2], bh[3]);
        }
    }
    __syncthreads();

    // ---- combine k-half partials through pbuf (48 cols, stride 64) ----
    const int r0 = ns * 16 + (lane >> 2);
    const int cb = (lane & 3) * 2;
    if (mh == 1) {
        #pragma unroll
        for (int tl = 0; tl < 6; tl++) {
            *(float2*)(gb + OFF_PB + (r0 * 64 + tl * 8 + cb) * 4)       = make_float2(c3a[tl][0], c3a[tl][1]);
            *(float2*)(gb + OFF_PB + ((r0 + 8) * 64 + tl * 8 + cb) * 4) = make_float2(c3a[tl][2], c3a[tl][3]);
        }
    }
    __syncthreads();
    if (mh == 0) {
        #pragma unroll
        for (int tl = 0; tl < 6; tl++) {
            float2 v0 = *(const float2*)(gb + OFF_PB + (r0 * 64 + tl * 8 + cb) * 4);
            float2 v1 = *(const float2*)(gb + OFF_PB + ((r0 + 8) * 64 + tl * 8 + cb) * 4);
            v0.x += c3a[tl][0]; v0.y += c3a[tl][1];
            v1.x += c3a[tl][2]; v1.y += c3a[tl][3];
            *(float2*)(gb + OFF_PB + (r0 * 64 + tl * 8 + cb) * 4)       = v0;
            *(float2*)(gb + OFF_PB + ((r0 + 8) * 64 + tl * 8 + cb) * 4) = v1;
        }
    }
    __syncthreads();

    // ---- epilogue (serial per-site, proven in R13) ----
    float ldj = 0.f;
    if (tid < MCTA) {
        const float* pr  = (const float*)(gb + OFF_PB) + tid * 64;
        const float* b3s = (const float*)(gb + OFF_B3S);
        float m = -1e30f, wl[KMIX];
        #pragma unroll
        for (int k = 0; k < KMIX; k++) { wl[k] = pr[32 + k] + b3s[32 + k]; m = fmaxf(m, wl[k]); }
        float se = 0.f, es[KMIX];
        #pragma unroll
        for (int k = 0; k < KMIX; k++) { es[k] = __expf(wl[k] - m); se += es[k]; }
        float inv_se = 1.f / se;
        float y = 0.f, dsum = 0.f;
        #pragma unroll
        for (int k = 0; k < KMIX; k++) {
            float lsc = pr[k] + b3s[k];
            float shf = pr[16 + k] + b3s[16 + k];
            float wgt = fmaf(es[k] * inv_se, 0.84f, 0.01f);
            float alpha = __expf(lsc);
            float xx = alpha * (lgt + shf);
            float gg = 1.f / (1.f + __expf(-xx));
            y = fmaf(wgt, gg, y);
            dsum = fmaf(wgt * alpha, gg * (1.f - gg), dsum);
        }
        float dy_du = dsum / (sv * (1.f - sv)) * dsdu;
        ldj = logf(dy_du);
        int idx = 3 * (chnk * MCTA + tid) + off;
        g_z[bat * LLEN + idx] = mod2pi(fmaf(TWO_PI_F, y, zr));
        #pragma unroll
        for (int o = 16; o; o >>= 1) ldj += __shfl_down_sync(0xffffffff, ldj, o);
        if (lane == 0) *(float*)(gb + OFF_LDJP + wp * 4) = ldj;
    }
    __syncthreads();
    if (tid == 0) {
        float s = 0.f;
        #pragma unroll
        for (int i = 0; i < 4; i++) s += *(const float*)(gb + OFF_LDJP + i * 4);
        g_part[t * GRID + blk] = s;
        __threadfence();
        *(volatile uint32_t*)&g_flag[t][blk] = 1u;
    }
}

__global__ void final_kernel(float* __restrict__ out, int out_size) {
    int i = blockIdx.x * blockDim.x + threadIdx.x;
    if (i < BATCH * LLEN && i < out_size) out[i] = g_z[i];
    if (blockIdx.x == 0 && threadIdx.x < BATCH) {
        int o = BATCH * LLEN + threadIdx.x;
        if (o < out_size) {
            float s = 0.f;
            for (int t = 0; t < NT; t++)
                for (int c = 0; c < 8; c++)
                    s += g_part[t * GRID + threadIdx.x * 8 + c];
            out[o] = s;
        }
    }
}

extern "C" void kernel_launch(void* const* d_in, const int* in_sizes, int n_in,
                              void* d_out, int out_size) {
    const float* z  = (const float*)d_in[0];
    const float* W1 = (const float*)d_in[1];
    const float* b1 = (const float*)d_in[2];
    const float* W2 = (const float*)d_in[3];
    const float* b2 = (const float*)d_in[4];
    const float* W3 = (const float*)d_in[5];
    const float* b3 = (const float*)d_in[6];
    float* out = (float*)d_out;

    static int attr_set = 0;
    if (!attr_set) {
        cudaFuncSetAttribute(step_kernel, cudaFuncAttributeMaxDynamicSharedMemorySize, SMEM_DYN);
        attr_set = 1;
    }

    prep_w2<<<(NT * 256 * 256 + 255) / 256, 256>>>(W2);
    prep_w3<<<(NT * 256 * 64 + 255) / 256, 256>>>(W3);
    init_kernel<<<(BATCH * LLEN + 255) / 256, 256>>>(z);

    const int off_tab[3] = {0, 2, 1};
    for (int t = 0; t < NT; t++) {
        cudaLaunchConfig_t cfg = {};
        cfg.gridDim = dim3(GRID, 1, 1);
        cfg.blockDim = dim3(THREADS, 1, 1);
        cfg.dynamicSmemBytes = SMEM_DYN;
        cfg.stream = 0;
        cudaLaunchAttribute at[1];
        at[0].id = cudaLaunchAttributeProgrammaticStreamSerialization;
        at[0].val.programmaticStreamSerializationAllowed = 1;
        cfg.attrs = at;
        cfg.numAttrs = (t > 0) ? 1 : 0;
        cudaLaunchKernelEx(&cfg, step_kernel, W1, b1, b2, b3, t, off_tab[t % 3]);
    }
    final_kernel<<<(BATCH * LLEN + 255) / 256, 256>>>(out, out_size);
}

// round 16
// speedup vs baseline: 1.5288x; 1.5288x over previous
#include <cuda_runtime.h>
#include <cuda_fp16.h>
#include <math.h>
#include <stdint.h>

#define TWO_PI_F   6.283185307179586f
#define INV_TWO_PI 0.15915494309189535f
#define NT    12
#define KMIX  16
#define HDIM  256
#define LLEN  3072
#define BATCH 64
#define EPSF  1e-6f
#define MCTA  128
#define GRID  512
#define THREADS 512

#define APITCH   528
#define APLANE   67584
#define OFF_A    0
#define B2PLANE  16896
#define OFF_B2_0 135168
#define OFF_B2_1 168960
#define B3PITCH  144
#define B3PLANE  36864
#define OFF_B3   135168
#define OFF_PB   0
#define OFF_C1   208896
#define OFF_C2   209408
#define OFF_B2S  209920
#define OFF_B3S  210944
#define OFF_LDJP 211200
#define SMEM_DYN 211456

__device__ float g_z[BATCH * LLEN];
__device__ float g_part[NT * GRID];
__device__ uint32_t g_flag[NT][GRID];
__device__ __align__(16) __half g_w2hi[NT * 256 * 256];
__device__ __align__(16) __half g_w2lo[NT * 256 * 256];
__device__ __align__(16) __half g_w3hi[NT * 256 * 64];
__device__ __align__(16) __half g_w3lo[NT * 256 * 64];

__device__ __forceinline__ float mod2pi(float x) {
    float r = fmodf(x, TWO_PI_F);
    return (r < 0.f) ? r + TWO_PI_F : r;
}
__device__ __forceinline__ float tanh_fast(float x) {
    float y; asm("tanh.approx.f32 %0, %1;" : "=f"(y) : "f"(x)); return y;
}
__device__ __forceinline__ uint32_t smem_u32(const void* p) {
    uint32_t a;
    asm("{ .reg .u64 t; cvta.to.shared.u64 t, %1; cvt.u32.u64 %0, t; }" : "=r"(a) : "l"(p));
    return a;
}
__device__ __forceinline__ uint32_t pack2h(float a, float b) {
    __half2 h = __floats2half2_rn(a, b);
    return *(uint32_t*)&h;
}

#define MMA(C, A, B0, B1) \
    asm volatile("mma.sync.aligned.m16n8k16.row.col.f32.f16.f16.f32 " \
        "{%0,%1,%2,%3},{%4,%5,%6,%7},{%8,%9},{%0,%1,%2,%3};" \
        : "+f"((C)[0]), "+f"((C)[1]), "+f"((C)[2]), "+f"((C)[3]) \
        : "r"((A)[0]), "r"((A)[1]), "r"((A)[2]), "r"((A)[3]), "r"(B0), "r"(B1))
#define LDSM4(R, a) \
    asm volatile("ldmatrix.sync.aligned.m8n8.x4.shared.b16 {%0,%1,%2,%3}, [%4];" \
        : "=r"((R)[0]), "=r"((R)[1]), "=r"((R)[2]), "=r"((R)[3]) : "r"(a))
#define LDSM4T(R, a) \
    asm volatile("ldmatrix.sync.aligned.m8n8.x4.trans.shared.b16 {%0,%1,%2,%3}, [%4];" \
        : "=r"((R)[0]), "=r"((R)[1]), "=r"((R)[2]), "=r"((R)[3]) : "r"(a))
#define CPASYNC16(d, s) asm volatile("cp.async.ca.shared.global [%0], [%1], 16;" :: "r"(d), "l"(s))
#define CPCOMMIT()      asm volatile("cp.async.commit_group;" ::: "memory")
#define CPWAIT0()       asm volatile("cp.async.wait_group 0;" ::: "memory")

__global__ void prep_w2(const float* __restrict__ W2) {
    int i = blockIdx.x * blockDim.x + threadIdx.x;
    if (i >= NT * 256 * 256) return;
    float v = W2[i];
    __half hi = __float2half_rn(v);
    g_w2hi[i] = hi;
    g_w2lo[i] = __float2half_rn(v - __half2float(hi));
}
__global__ void prep_w3(const float* __restrict__ W3) {
    int i = blockIdx.x * blockDim.x + threadIdx.x;
    if (i >= NT * 256 * 64) return;
    int n = i & 63, k = (i >> 6) & 255, t = i >> 14;
    float v = (n < 48) ? W3[((size_t)t * 256 + k) * 48 + n] : 0.f;
    __half hi = __float2half_rn(v);
    g_w3hi[i] = hi;
    g_w3lo[i] = __float2half_rn(v - __half2float(hi));
}
__global__ void init_kernel(const float* __restrict__ z_in) {
    int i = blockIdx.x * blockDim.x + threadIdx.x;
    if (i < BATCH * LLEN) g_z[i] = z_in[i];
    if (i < NT * GRID) ((uint32_t*)g_flag)[i] = 0u;
}

__global__ __launch_bounds__(THREADS, 1)
void step_kernel(const float* __restrict__ W1, const float* __restrict__ b1,
                 const float* __restrict__ b2, const float* __restrict__ b3,
                 int t, int off)
{
    cudaTriggerProgrammaticLaunchCompletion();

    extern __shared__ __align__(16) char dsm[];
    const uint32_t base = smem_u32(dsm);
    char* gb = dsm;

    const int tid  = threadIdx.x;
    const int lane = tid & 31;
    const int wp   = tid >> 5;
    const int mh   = wp >> 3;
    const int ns   = wp & 7;
    const int blk  = blockIdx.x;
    const int bat  = blk >> 3;
    const int chnk = blk & 7;

    const float* W1t = W1 + t * 2 * HDIM;
    const float* b1t = b1 + t * HDIM;
    const float* zrow = g_z + bat * LLEN;

    // ---- z-independent prologue: biases + B2 chunk 0 prefetch ----
    if (tid < 64) {
        *(float4*)(gb + OFF_B2S + tid * 16) = __ldg((const float4*)&b2[t * 256 + tid * 4]);
    } else if (tid < 76) {
        *(float4*)(gb + OFF_B3S + (tid - 64) * 16) = __ldg((const float4*)&b3[t * 48 + (tid - 64) * 4]);
    }
    for (int i = tid; i < 2048; i += THREADS) {
        int p = i >> 10, r = (i >> 5) & 31, seg = i & 31;
        const __half* src = (p ? g_w2lo : g_w2hi) + ((size_t)(t * 256 + r) * 256 + seg * 8);
        CPASYNC16(base + OFF_B2_0 + p * B2PLANE + r * APITCH + seg * 16, src);
    }
    CPCOMMIT();

    // ---- wait for producer chunks of previous step (c-1, c, c+1) ----
    if (t > 0) {
        if (tid < 3) {
            int nb = (chnk + tid + 7) & 7;
            volatile uint32_t* f = &g_flag[t - 1][bat * 8 + nb];
            while (*f == 0u) { }
        }
        __threadfence();
    }
    __syncthreads();

    // ---- phase 0: per-site context ----
    float sv = 0.f, dsdu = 0.f, lgt = 0.f, zr = 0.f;
    if (tid < MCTA) {
        int idx = 3 * (chnk * MCTA + tid) + off;
        int im2 = idx - 2; if (im2 < 0) im2 += LLEN;
        int im1 = idx - 1; if (im1 < 0) im1 += LLEN;
        int ip1 = idx + 1; if (ip1 >= LLEN) ip1 -= LLEN;
        int ip2 = idx + 2; if (ip2 >= LLEN) ip2 -= LLEN;
        float zm2 = zrow[im2], zm1 = zrow[im1], z0 = zrow[idx];
        float zp1 = zrow[ip1], zp2 = zrow[ip2];
        *(float*)(gb + OFF_C1 + tid * 4) = mod2pi(zm1 - zm2);
        *(float*)(gb + OFF_C2 + tid * 4) = mod2pi(zp2 - zp1);
        float Vc = mod2pi(z0 - zm1);
        float u = fminf(fmaxf(Vc * INV_TWO_PI, EPSF), 1.f - EPSF);
        float a = u * u, bb = (1.f - u) * (1.f - u);
        float den = a + bb;
        sv = a / den;
        dsdu = 2.f * u * (1.f - u) / (den * den);
        sv = fminf(fmaxf(sv, EPSF), 1.f - EPSF);
        lgt = logf(sv) - log1pf(-sv);
        zr = zm1;
    }
    __syncthreads();

    // ---- layer 1: h1 -> A tile (fp16 hi + lo planes) ----
    {
        const int p = tid & 127, sh = tid >> 7;
        float w00 = __ldg(&W1t[2 * p]),       w01 = __ldg(&W1t[2 * p + 1]);
        float w10 = __ldg(&W1t[256 + 2 * p]), w11 = __ldg(&W1t[256 + 2 * p + 1]);
        float bb0 = __ldg(&b1t[2 * p]),       bb1 = __ldg(&b1t[2 * p + 1]);
        for (int s = sh * 32; s < sh * 32 + 32; s++) {
            float c1 = *(const float*)(gb + OFF_C1 + s * 4);
            float c2 = *(const float*)(gb + OFF_C2 + s * 4);
            float x0 = tanh_fast(fmaf(c1, w00, fmaf(c2, w10, bb0)));
            float x1 = tanh_fast(fmaf(c1, w01, fmaf(c2, w11, bb1)));
            __half h0 = __float2half_rn(x0), h1v = __float2half_rn(x1);
            float l0 = x0 - __half2float(h0), l1 = x1 - __half2float(h1v);
            *(uint32_t*)(gb + OFF_A + s * APITCH + 4 * p)          = pack2h(x0, x1);
            *(uint32_t*)(gb + OFF_A + APLANE + s * APITCH + 4 * p) = pack2h(l0, l1);
        }
    }
    CPWAIT0();
    __syncthreads();

    const int lr8   = ((lane >> 3) & 1) * 8 + (lane & 7);
    const int chalf = lane >> 4;

    // ---- GEMM2 ----
    float cacc[16][4];
    #pragma unroll
    for (int i = 0; i < 16; i++) { cacc[i][0]=0.f; cacc[i][1]=0.f; cacc[i][2]=0.f; cacc[i][3]=0.f; }

    const uint32_t aB2 = base + OFF_A + (mh * 64 + lr8) * APITCH + chalf * 16;

    #pragma unroll 1
    for (int c = 0; c < 8; c++) {
        const uint32_t bufc = (c & 1) ? (base + OFF_B2_1) : (base + OFF_B2_0);
        if (c < 7) {
            const uint32_t bufn = ((c + 1) & 1) ? (base + OFF_B2_1) : (base + OFF_B2_0);
            for (int i = tid; i < 2048; i += THREADS) {
                int p = i >> 10, r = (i >> 5) & 31, seg = i & 31;
                const __half* src = (p ? g_w2lo : g_w2hi) +
                    ((size_t)(t * 256 + (c + 1) * 32 + r) * 256 + seg * 8);
                CPASYNC16(bufn + p * B2PLANE + r * APITCH + seg * 16, src);
            }
            CPCOMMIT();
        }
        #pragma unroll
        for (int s = 0; s < 2; s++) {
            const int k = c * 32 + s * 16;
            uint32_t ah[4][4], al[4][4];
            #pragma unroll
            for (int mt = 0; mt < 4; mt++) {
                LDSM4(ah[mt], aB2 + mt * 16 * APITCH + k * 2);
                LDSM4(al[mt], aB2 + APLANE + mt * 16 * APITCH + k * 2);
            }
            const uint32_t brow = bufc + (s * 16 + lr8) * APITCH + ns * 64 + chalf * 16;
            #pragma unroll
            for (int nt = 0; nt < 2; nt++) {
                uint32_t bh[4], bl[4];
                LDSM4T(bh, brow + nt * 32);
                LDSM4T(bl, brow + nt * 32 + B2PLANE);
                #pragma unroll
                for (int mt = 0; mt < 4; mt++) {
                    MMA(cacc[mt * 4 + nt * 2],     ah[mt], bh[0], bh[1]);
                    MMA(cacc[mt * 4 + nt * 2 + 1], ah[mt], bh[2], bh[3]);
                    MMA(cacc[mt * 4 + nt * 2],     ah[mt], bl[0], bl[1]);
                    MMA(cacc[mt * 4 + nt * 2 + 1], ah[mt], bl[2], bl[3]);
                    MMA(cacc[mt * 4 + nt * 2],     al[mt], bh[0], bh[1]);
                    MMA(cacc[mt * 4 + nt * 2 + 1], al[mt], bh[2], bh[3]);
                }
            }
        }
        CPWAIT0();
        __syncthreads();
    }

    // ---- prefetch B3 (hi+lo), 48 real cols only (6 of 8 segs/row) ----
    for (int i = tid; i < 3072; i += THREADS) {
        int p = (i >= 1536), rem = p ? (i - 1536) : i;
        int r = rem / 6, seg = rem % 6;
        const __half* src = (p ? g_w3lo : g_w3hi) + ((size_t)(t * 256 + r) * 64 + seg * 8);
        CPASYNC16(base + OFF_B3 + p * B3PLANE + r * B3PITCH + seg * 16, src);
    }
    CPCOMMIT();

    // ---- convert C2 -> h2 (fp16 hi+lo) ----
    {
        #pragma unroll
        for (int mt = 0; mt < 4; mt++) {
            const int rowA = mh * 64 + mt * 16 + (lane >> 2);
            #pragma unroll
            for (int q = 0; q < 4; q++) {
                const int col = ns * 32 + q * 8 + (lane & 3) * 2;
                float2 bb = *(const float2*)(gb + OFF_B2S + col * 4);
                float x0 = tanh_fast(cacc[mt * 4 + q][0] + bb.x);
                float x1 = tanh_fast(cacc[mt * 4 + q][1] + bb.y);
                float x2 = tanh_fast(cacc[mt * 4 + q][2] + bb.x);
                float x3 = tanh_fast(cacc[mt * 4 + q][3] + bb.y);
                __half q0 = __float2half_rn(x0), q1 = __float2half_rn(x1);
                __half q2 = __float2half_rn(x2), q3 = __float2half_rn(x3);
                *(uint32_t*)(gb + OFF_A + rowA * APITCH + col * 2)       = pack2h(x0, x1);
                *(uint32_t*)(gb + OFF_A + (rowA + 8) * APITCH + col * 2) = pack2h(x2, x3);
                *(uint32_t*)(gb + OFF_A + APLANE + rowA * APITCH + col * 2) =
                    pack2h(x0 - __half2float(q0), x1 - __half2float(q1));
                *(uint32_t*)(gb + OFF_A + APLANE + (rowA + 8) * APITCH + col * 2) =
                    pack2h(x2 - __half2float(q2), x3 - __half2float(q3));
            }
        }
    }
    CPWAIT0();
    __syncthreads();

    // ---- GEMM3: 48 real columns only (np < 3; cols 48..63 are zero weights) ----
    float c3a[6][4];
    #pragma unroll
    for (int i = 0; i < 6; i++) { c3a[i][0]=0.f; c3a[i][1]=0.f; c3a[i][2]=0.f; c3a[i][3]=0.f; }
    const uint32_t aB3 = base + OFF_A + (ns * 16 + lr8) * APITCH + chalf * 16;
    #pragma unroll
    for (int j = 0; j < 8; j++) {
        const int k = mh * 128 + j * 16;
        uint32_t a3h[4], a3l[4];
        LDSM4(a3h, aB3 + k * 2);
        LDSM4(a3l, aB3 + APLANE + k * 2);
        const uint32_t b3row = base + OFF_B3 + (k + lr8) * B3PITCH + chalf * 16;
        #pragma unroll
        for (int np = 0; np < 3; np++) {
            uint32_t bh[4], bl[4];
            LDSM4T(bh, b3row + np * 32);
            LDSM4T(bl, b3row + np * 32 + B3PLANE);
            MMA(c3a[2 * np],     a3h, bh[0], bh[1]);
            MMA(c3a[2 * np + 1], a3h, bh[2], bh[3]);
            MMA(c3a[2 * np],     a3h, bl[0], bl[1]);
            MMA(c3a[2 * np + 1], a3h, bl[2], bl[3]);
            MMA(c3a[2 * np],     a3l, bh[0], bh[1]);
            MMA(c3a[2 * np + 1], a3l, bh[2], bh[3]);
        }
    }
    __syncthreads();

    // ---- combine k-half partials through pbuf (48 cols, stride 64) ----
    const int r0 = ns * 16 + (lane >> 2);
    const int cb = (lane & 3) * 2;
    if (mh == 1) {
        #pragma unroll
        for (int tl = 0; tl < 6; tl++) {
            *(float2*)(gb + OFF_PB + (r0 * 64 + tl * 8 + cb) * 4)       = make_float2(c3a[tl][0], c3a[tl][1]);
            *(float2*)(gb + OFF_PB + ((r0 + 8) * 64 + tl * 8 + cb) * 4) = make_float2(c3a[tl][2], c3a[tl][3]);
        }
    }
    __syncthreads();
    if (mh == 0) {
        #pragma unroll
        for (int tl = 0; tl < 6; tl++) {
            float2 v0 = *(const float2*)(gb + OFF_PB + (r0 * 64 + tl * 8 + cb) * 4);
            float2 v1 = *(const float2*)(gb + OFF_PB + ((r0 + 8) * 64 + tl * 8 + cb) * 4);
            v0.x += c3a[tl][0]; v0.y += c3a[tl][1];
            v1.x += c3a[tl][2]; v1.y += c3a[tl][3];
            *(float2*)(gb + OFF_PB + (r0 * 64 + tl * 8 + cb) * 4)       = v0;
            *(float2*)(gb + OFF_PB + ((r0 + 8) * 64 + tl * 8 + cb) * 4) = v1;
        }
    }
    __syncthreads();

    // ---- epilogue (serial per-site, proven in R13) ----
    float ldj = 0.f;
    if (tid < MCTA) {
        const float* pr  = (const float*)(gb + OFF_PB) + tid * 64;
        const float* b3s = (const float*)(gb + OFF_B3S);
        float m = -1e30f, wl[KMIX];
        #pragma unroll
        for (int k = 0; k < KMIX; k++) { wl[k] = pr[32 + k] + b3s[32 + k]; m = fmaxf(m, wl[k]); }
        float se = 0.f, es[KMIX];
        #pragma unroll
        for (int k = 0; k < KMIX; k++) { es[k] = __expf(wl[k] - m); se += es[k]; }
        float inv_se = 1.f / se;
        float y = 0.f, dsum = 0.f;
        #pragma unroll
        for (int k = 0; k < KMIX; k++) {
            float lsc = pr[k] + b3s[k];
            float shf = pr[16 + k] + b3s[16 + k];
            float wgt = fmaf(es[k] * inv_se, 0.84f, 0.01f);
            float alpha = __expf(lsc);
            float xx = alpha * (lgt + shf);
            float gg = 1.f / (1.f + __expf(-xx));
            y = fmaf(wgt, gg, y);
            dsum = fmaf(wgt * alpha, gg * (1.f - gg), dsum);
        }
        float dy_du = dsum / (sv * (1.f - sv)) * dsdu;
        ldj = logf(dy_du);
        int idx = 3 * (chnk * MCTA + tid) + off;
        g_z[bat * LLEN + idx] = mod2pi(fmaf(TWO_PI_F, y, zr));
        #pragma unroll
        for (int o = 16; o; o >>= 1) ldj += __shfl_down_sync(0xffffffff, ldj, o);
        if (lane == 0) *(float*)(gb + OFF_LDJP + wp * 4) = ldj;
    }
    __syncthreads();
    if (tid == 0) {
        float s = 0.f;
        #pragma unroll
        for (int i = 0; i < 4; i++) s += *(const float*)(gb + OFF_LDJP + i * 4);
        g_part[t * GRID + blk] = s;
        __threadfence();
        *(volatile uint32_t*)&g_flag[t][blk] = 1u;
    }
}

__global__ void final_kernel(float* __restrict__ out, int out_size) {
    int i = blockIdx.x * blockDim.x + threadIdx.x;
    if (i < BATCH * LLEN && i < out_size) out[i] = g_z[i];
    if (blockIdx.x == 0 && threadIdx.x < BATCH) {
        int o = BATCH * LLEN + threadIdx.x;
        if (o < out_size) {
            float s = 0.f;
            for (int t = 0; t < NT; t++)
                for (int c = 0; c < 8; c++)
                    s += g_part[t * GRID + threadIdx.x * 8 + c];
            out[o] = s;
        }
    }
}

extern "C" void kernel_launch(void* const* d_in, const int* in_sizes, int n_in,
                              void* d_out, int out_size) {
    const float* z  = (const float*)d_in[0];
    const float* W1 = (const float*)d_in[1];
    const float* b1 = (const float*)d_in[2];
    const float* W2 = (const float*)d_in[3];
    const float* b2 = (const float*)d_in[4];
    const float* W3 = (const float*)d_in[5];
    const float* b3 = (const float*)d_in[6];
    float* out = (float*)d_out;

    static int attr_set = 0;
    if (!attr_set) {
        cudaFuncSetAttribute(step_kernel, cudaFuncAttributeMaxDynamicSharedMemorySize, SMEM_DYN);
        attr_set = 1;
    }

    prep_w2<<<(NT * 256 * 256 + 255) / 256, 256>>>(W2);
    prep_w3<<<(NT * 256 * 64 + 255) / 256, 256>>>(W3);
    init_kernel<<<(BATCH * LLEN + 255) / 256, 256>>>(z);

    const int off_tab[3] = {0, 2, 1};
    for (int t = 0; t < NT; t++) {
        cudaLaunchConfig_t cfg = {};
        cfg.gridDim = dim3(GRID, 1, 1);
        cfg.blockDim = dim3(THREADS, 1, 1);
        cfg.dynamicSmemBytes = SMEM_DYN;
        cfg.stream = 0;
        cudaLaunchAttribute at[1];
        at[0].id = cudaLaunchAttributeProgrammaticStreamSerialization;
        at[0].val.programmaticStreamSerializationAllowed = 1;
        cfg.attrs = at;
        cfg.numAttrs = (t > 0) ? 1 : 0;
        cudaLaunchKernelEx(&cfg, step_kernel, W1, b1, b2, b3, t, off_tab[t % 3]);
    }
    final_kernel<<<(BATCH * LLEN + 255) / 256, 256>>>(out, out_size);
}

// round 17
// speedup vs baseline: 1.6372x; 1.0709x over previous
#include <cuda_runtime.h>
#include <cuda_fp16.h>
#include <math.h>
#include <stdint.h>

#define TWO_PI_F   6.283185307179586f
#define INV_TWO_PI 0.15915494309189535f
#define NT    12
#define KMIX  16
#define HDIM  256
#define LLEN  3072
#define BATCH 64
#define EPSF  1e-6f
#define MCTA  64
#define GRID  1024
#define THREADS 256

#define APITCH   528
#define APLANE   33792                  // 64 x 528 per plane
#define OFF_A    0                      // hi|lo planes: 67584
#define OFF_B2   67584                  // 32 x 528 x 2 planes = 33792
#define B2PLANE  16896
#define B3PITCH  112
#define B3PLANE_C 14336                 // 128 rows x 112
#define OFF_PB   67584                  // 64 x 64 f32 = 16384, overlays B2/B3
#define OFF_C1   101376
#define OFF_C2   101632
#define OFF_B2S  101888
#define OFF_B3S  102912
#define OFF_LDJP 103104
#define SMEM_DYN 103424

__device__ float g_z[BATCH * LLEN];
__device__ float g_part[NT * GRID];
__device__ uint32_t g_flag[NT][GRID];
__device__ __align__(16) __half g_w2hi[NT * 256 * 256];
__device__ __align__(16) __half g_w2lo[NT * 256 * 256];
__device__ __align__(16) __half g_w3hi[NT * 256 * 64];
__device__ __align__(16) __half g_w3lo[NT * 256 * 64];

__device__ __forceinline__ float mod2pi(float x) {
    float r = fmodf(x, TWO_PI_F);
    return (r < 0.f) ? r + TWO_PI_F : r;
}
__device__ __forceinline__ float tanh_fast(float x) {
    float y; asm("tanh.approx.f32 %0, %1;" : "=f"(y) : "f"(x)); return y;
}
__device__ __forceinline__ uint32_t smem_u32(const void* p) {
    uint32_t a;
    asm("{ .reg .u64 t; cvta.to.shared.u64 t, %1; cvt.u32.u64 %0, t; }" : "=r"(a) : "l"(p));
    return a;
}
__device__ __forceinline__ uint32_t pack2h(float a, float b) {
    __half2 h = __floats2half2_rn(a, b);
    return *(uint32_t*)&h;
}

#define MMA(C, A, B0, B1) \
    asm volatile("mma.sync.aligned.m16n8k16.row.col.f32.f16.f16.f32 " \
        "{%0,%1,%2,%3},{%4,%5,%6,%7},{%8,%9},{%0,%1,%2,%3};" \
        : "+f"((C)[0]), "+f"((C)[1]), "+f"((C)[2]), "+f"((C)[3]) \
        : "r"((A)[0]), "r"((A)[1]), "r"((A)[2]), "r"((A)[3]), "r"(B0), "r"(B1))
#define LDSM4(R, a) \
    asm volatile("ldmatrix.sync.aligned.m8n8.x4.shared.b16 {%0,%1,%2,%3}, [%4];" \
        : "=r"((R)[0]), "=r"((R)[1]), "=r"((R)[2]), "=r"((R)[3]) : "r"(a))
#define LDSM4T(R, a) \
    asm volatile("ldmatrix.sync.aligned.m8n8.x4.trans.shared.b16 {%0,%1,%2,%3}, [%4];" \
        : "=r"((R)[0]), "=r"((R)[1]), "=r"((R)[2]), "=r"((R)[3]) : "r"(a))
#define CPASYNC16(d, s) asm volatile("cp.async.ca.shared.global [%0], [%1], 16;" :: "r"(d), "l"(s))
#define CPCOMMIT()      asm volatile("cp.async.commit_group;" ::: "memory")
#define CPWAIT0()       asm volatile("cp.async.wait_group 0;" ::: "memory")

__global__ void prep_w2(const float* __restrict__ W2) {
    int i = blockIdx.x * blockDim.x + threadIdx.x;
    if (i >= NT * 256 * 256) return;
    float v = W2[i];
    __half hi = __float2half_rn(v);
    g_w2hi[i] = hi;
    g_w2lo[i] = __float2half_rn(v - __half2float(hi));
}
__global__ void prep_w3(const float* __restrict__ W3) {
    int i = blockIdx.x * blockDim.x + threadIdx.x;
    if (i >= NT * 256 * 64) return;
    int n = i & 63, k = (i >> 6) & 255, t = i >> 14;
    float v = (n < 48) ? W3[((size_t)t * 256 + k) * 48 + n] : 0.f;
    __half hi = __float2half_rn(v);
    g_w3hi[i] = hi;
    g_w3lo[i] = __float2half_rn(v - __half2float(hi));
}
__global__ void init_kernel(const float* __restrict__ z_in) {
    int i = blockIdx.x * blockDim.x + threadIdx.x;
    if (i < BATCH * LLEN) g_z[i] = z_in[i];
    if (i < NT * GRID) ((uint32_t*)g_flag)[i] = 0u;
}

__global__ __launch_bounds__(THREADS, 2)
void step_kernel(const float* __restrict__ W1, const float* __restrict__ b1,
                 const float* __restrict__ b2, const float* __restrict__ b3,
                 int t, int off)
{
    cudaTriggerProgrammaticLaunchCompletion();

    extern __shared__ __align__(16) char dsm[];
    const uint32_t base = smem_u32(dsm);
    char* gb = dsm;

    const int tid  = threadIdx.x;
    const int lane = tid & 31;
    const int wp   = tid >> 5;
    const int mh   = wp >> 2;      // GEMM2: m-half (32 rows) | GEMM3: k-j-half
    const int ns   = wp & 3;       // GEMM2: n-slice (64 cols) | GEMM3: row strip (16)
    const int blk  = blockIdx.x;
    const int bat  = blk >> 4;
    const int chnk = blk & 15;

    const float* W1t = W1 + t * 2 * HDIM;
    const float* b1t = b1 + t * HDIM;
    const float* zrow = g_z + bat * LLEN;

    // ---- z-independent prologue: biases + B2 chunk 0 prefetch ----
    if (tid < 64) {
        *(float4*)(gb + OFF_B2S + tid * 16) = __ldg((const float4*)&b2[t * 256 + tid * 4]);
    } else if (tid < 76) {
        *(float4*)(gb + OFF_B3S + (tid - 64) * 16) = __ldg((const float4*)&b3[t * 48 + (tid - 64) * 4]);
    }
    for (int i = tid; i < 2048; i += THREADS) {
        int p = i >> 10, r = (i >> 5) & 31, seg = i & 31;
        const __half* src = (p ? g_w2lo : g_w2hi) + ((size_t)(t * 256 + r) * 256 + seg * 8);
        CPASYNC16(base + OFF_B2 + p * B2PLANE + r * APITCH + seg * 16, src);
    }
    CPCOMMIT();

    // ---- wait for producer chunks of previous step (c-1, c, c+1 of 16) ----
    if (t > 0) {
        if (tid < 3) {
            int nb = (chnk + tid + 15) & 15;
            volatile uint32_t* f = &g_flag[t - 1][bat * 16 + nb];
            while (*f == 0u) { }
        }
        __threadfence();
    }
    __syncthreads();

    // ---- phase 0: per-site context (tid < 64 = site) ----
    float sv = 0.f, dsdu = 0.f, lgt = 0.f, zr = 0.f;
    if (tid < MCTA) {
        int idx = 3 * (chnk * MCTA + tid) + off;
        int im2 = idx - 2; if (im2 < 0) im2 += LLEN;
        int im1 = idx - 1; if (im1 < 0) im1 += LLEN;
        int ip1 = idx + 1; if (ip1 >= LLEN) ip1 -= LLEN;
        int ip2 = idx + 2; if (ip2 >= LLEN) ip2 -= LLEN;
        float zm2 = zrow[im2], zm1 = zrow[im1], z0 = zrow[idx];
        float zp1 = zrow[ip1], zp2 = zrow[ip2];
        *(float*)(gb + OFF_C1 + tid * 4) = mod2pi(zm1 - zm2);
        *(float*)(gb + OFF_C2 + tid * 4) = mod2pi(zp2 - zp1);
        float Vc = mod2pi(z0 - zm1);
        float u = fminf(fmaxf(Vc * INV_TWO_PI, EPSF), 1.f - EPSF);
        float a = u * u, bb = (1.f - u) * (1.f - u);
        float den = a + bb;
        sv = a / den;
        dsdu = 2.f * u * (1.f - u) / (den * den);
        sv = fminf(fmaxf(sv, EPSF), 1.f - EPSF);
        lgt = logf(sv) - log1pf(-sv);
        zr = zm1;
    }
    __syncthreads();

    // ---- layer 1: h1 -> A tile (fp16 hi + lo planes); 64 sites ----
    {
        const int p = tid & 127, sh = tid >> 7;   // sh 0..1, 32 sites each
        float w00 = __ldg(&W1t[2 * p]),       w01 = __ldg(&W1t[2 * p + 1]);
        float w10 = __ldg(&W1t[256 + 2 * p]), w11 = __ldg(&W1t[256 + 2 * p + 1]);
        float bb0 = __ldg(&b1t[2 * p]),       bb1 = __ldg(&b1t[2 * p + 1]);
        for (int s = sh * 32; s < sh * 32 + 32; s++) {
            float c1 = *(const float*)(gb + OFF_C1 + s * 4);
            float c2 = *(const float*)(gb + OFF_C2 + s * 4);
            float x0 = tanh_fast(fmaf(c1, w00, fmaf(c2, w10, bb0)));
            float x1 = tanh_fast(fmaf(c1, w01, fmaf(c2, w11, bb1)));
            __half h0 = __float2half_rn(x0), h1v = __float2half_rn(x1);
            float l0 = x0 - __half2float(h0), l1 = x1 - __half2float(h1v);
            *(uint32_t*)(gb + OFF_A + s * APITCH + 4 * p)          = pack2h(x0, x1);
            *(uint32_t*)(gb + OFF_A + APLANE + s * APITCH + 4 * p) = pack2h(l0, l1);
        }
    }
    CPWAIT0();
    __syncthreads();   // A(h1) ready + B2 chunk 0 ready

    const int lr8   = ((lane >> 3) & 1) * 8 + (lane & 7);
    const int chalf = lane >> 4;

    // ---- GEMM2: warp (mh, ns): rows 32mh..+31 (2 m-tiles) x cols 64ns..+63 ----
    float cacc[16][4];
    #pragma unroll
    for (int i = 0; i < 16; i++) { cacc[i][0]=0.f; cacc[i][1]=0.f; cacc[i][2]=0.f; cacc[i][3]=0.f; }

    const uint32_t aB2 = base + OFF_A + (mh * 32 + lr8) * APITCH + chalf * 16;

    #pragma unroll 1
    for (int c = 0; c < 8; c++) {
        #pragma unroll
        for (int s = 0; s < 2; s++) {
            const int k = c * 32 + s * 16;
            uint32_t ah[2][4], al[2][4];
            #pragma unroll
            for (int mt = 0; mt < 2; mt++) {
                LDSM4(ah[mt], aB2 + mt * 16 * APITCH + k * 2);
                LDSM4(al[mt], aB2 + APLANE + mt * 16 * APITCH + k * 2);
            }
            const uint32_t brow = base + OFF_B2 + (s * 16 + lr8) * APITCH + ns * 128 + chalf * 16;
            #pragma unroll
            for (int nt = 0; nt < 4; nt++) {
                uint32_t bh[4], bl[4];
                LDSM4T(bh, brow + nt * 32);
                LDSM4T(bl, brow + nt * 32 + B2PLANE);
                #pragma unroll
                for (int mt = 0; mt < 2; mt++) {
                    MMA(cacc[mt * 8 + nt * 2],     ah[mt], bh[0], bh[1]);
                    MMA(cacc[mt * 8 + nt * 2 + 1], ah[mt], bh[2], bh[3]);
                    MMA(cacc[mt * 8 + nt * 2],     ah[mt], bl[0], bl[1]);
                    MMA(cacc[mt * 8 + nt * 2 + 1], ah[mt], bl[2], bl[3]);
                    MMA(cacc[mt * 8 + nt * 2],     al[mt], bh[0], bh[1]);
                    MMA(cacc[mt * 8 + nt * 2 + 1], al[mt], bh[2], bh[3]);
                }
            }
        }
        __syncthreads();   // all reads of this chunk done
        if (c < 7) {
            for (int i = tid; i < 2048; i += THREADS) {
                int p = i >> 10, r = (i >> 5) & 31, seg = i & 31;
                const __half* src = (p ? g_w2lo : g_w2hi) +
                    ((size_t)(t * 256 + (c + 1) * 32 + r) * 256 + seg * 8);
                CPASYNC16(base + OFF_B2 + p * B2PLANE + r * APITCH + seg * 16, src);
            }
            CPCOMMIT();
            CPWAIT0();
            __syncthreads();
        }
    }

    // ---- B3 chunk 0 load (overwrites B2 buffer) + h2 convert overlap ----
    for (int i = tid; i < 1536; i += THREADS) {
        int p = (i >= 768);
        int rem = i - p * 768;
        int r = rem / 6, seg = rem - r * 6;
        const __half* src = (p ? g_w3lo : g_w3hi) + ((size_t)(t * 256 + r) * 64 + seg * 8);
        CPASYNC16(base + OFF_B2 + p * B3PLANE_C + r * B3PITCH + seg * 16, src);
    }
    CPCOMMIT();

    // convert C2 -> h2 (fp16 hi+lo) into A planes
    {
        #pragma unroll
        for (int mt = 0; mt < 2; mt++) {
            const int rowA = mh * 32 + mt * 16 + (lane >> 2);
            #pragma unroll
            for (int q = 0; q < 8; q++) {
                const int col = ns * 64 + q * 8 + (lane & 3) * 2;
                float2 bb = *(const float2*)(gb + OFF_B2S + col * 4);
                float x0 = tanh_fast(cacc[mt * 8 + q][0] + bb.x);
                float x1 = tanh_fast(cacc[mt * 8 + q][1] + bb.y);
                float x2 = tanh_fast(cacc[mt * 8 + q][2] + bb.x);
                float x3 = tanh_fast(cacc[mt * 8 + q][3] + bb.y);
                __half q0 = __float2half_rn(x0), q1 = __float2half_rn(x1);
                __half q2 = __float2half_rn(x2), q3 = __float2half_rn(x3);
                *(uint32_t*)(gb + OFF_A + rowA * APITCH + col * 2)       = pack2h(x0, x1);
                *(uint32_t*)(gb + OFF_A + (rowA + 8) * APITCH + col * 2) = pack2h(x2, x3);
                *(uint32_t*)(gb + OFF_A + APLANE + rowA * APITCH + col * 2) =
                    pack2h(x0 - __half2float(q0), x1 - __half2float(q1));
                *(uint32_t*)(gb + OFF_A + APLANE + (rowA + 8) * APITCH + col * 2) =
                    pack2h(x2 - __half2float(q2), x3 - __half2float(q3));
            }
        }
    }
    CPWAIT0();
    __syncthreads();   // h2 + B3 chunk 0 ready

    // ---- GEMM3: warp (mh = j-half, ns = 16-row strip); K in 2 chunks ----
    float c3a[6][4];
    #pragma unroll
    for (int i = 0; i < 6; i++) { c3a[i][0]=0.f; c3a[i][1]=0.f; c3a[i][2]=0.f; c3a[i][3]=0.f; }
    const uint32_t aB3 = base + OFF_A + (ns * 16 + lr8) * APITCH + chalf * 16;
    #pragma unroll 1
    for (int ch = 0; ch < 2; ch++) {
        #pragma unroll
        for (int jj = 0; jj < 4; jj++) {
            const int j = mh * 4 + jj;             // chunk-local k16 block
            const int kg = ch * 128 + j * 16;      // global k
            uint32_t a3h[4], a3l[4];
            LDSM4(a3h, aB3 + kg * 2);
            LDSM4(a3l, aB3 + APLANE + kg * 2);
            const uint32_t b3row = base + OFF_B2 + (j * 16 + lr8) * B3PITCH + chalf * 16;
            #pragma unroll
            for (int np = 0; np < 3; np++) {
                uint32_t bh[4], bl[4];
                LDSM4T(bh, b3row + np * 32);
                LDSM4T(bl, b3row + np * 32 + B3PLANE_C);
                MMA(c3a[2 * np],     a3h, bh[0], bh[1]);
                MMA(c3a[2 * np + 1], a3h, bh[2], bh[3]);
                MMA(c3a[2 * np],     a3h, bl[0], bl[1]);
                MMA(c3a[2 * np + 1], a3h, bl[2], bl[3]);
                MMA(c3a[2 * np],     a3l, bh[0], bh[1]);
                MMA(c3a[2 * np + 1], a3l, bh[2], bh[3]);
            }
        }
        __syncthreads();   // chunk reads done
        if (ch == 0) {
            for (int i = tid; i < 1536; i += THREADS) {
                int p = (i >= 768);
                int rem = i - p * 768;
                int r = rem / 6, seg = rem - r * 6;
                const __half* src = (p ? g_w3lo : g_w3hi) +
                    ((size_t)(t * 256 + 128 + r) * 64 + seg * 8);
                CPASYNC16(base + OFF_B2 + p * B3PLANE_C + r * B3PITCH + seg * 16, src);
            }
            CPCOMMIT();
            CPWAIT0();
            __syncthreads();
        }
    }

    // ---- combine j-half partials through pbuf (overlays dead B3 buffer) ----
    const int r0 = ns * 16 + (lane >> 2);
    const int cb = (lane & 3) * 2;
    if (mh == 1) {
        #pragma unroll
        for (int tl = 0; tl < 6; tl++) {
            *(float2*)(gb + OFF_PB + (r0 * 64 + tl * 8 + cb) * 4)       = make_float2(c3a[tl][0], c3a[tl][1]);
            *(float2*)(gb + OFF_PB + ((r0 + 8) * 64 + tl * 8 + cb) * 4) = make_float2(c3a[tl][2], c3a[tl][3]);
        }
    }
    __syncthreads();
    if (mh == 0) {
        #pragma unroll
        for (int tl = 0; tl < 6; tl++) {
            float2 v0 = *(const float2*)(gb + OFF_PB + (r0 * 64 + tl * 8 + cb) * 4);
            float2 v1 = *(const float2*)(gb + OFF_PB + ((r0 + 8) * 64 + tl * 8 + cb) * 4);
            v0.x += c3a[tl][0]; v0.y += c3a[tl][1];
            v1.x += c3a[tl][2]; v1.y += c3a[tl][3];
            *(float2*)(gb + OFF_PB + (r0 * 64 + tl * 8 + cb) * 4)       = v0;
            *(float2*)(gb + OFF_PB + ((r0 + 8) * 64 + tl * 8 + cb) * 4) = v1;
        }
    }
    __syncthreads();

    // ---- epilogue (serial per-site, register-carried context) ----
    float ldj = 0.f;
    if (tid < MCTA) {
        const float* pr  = (const float*)(gb + OFF_PB) + tid * 64;
        const float* b3s = (const float*)(gb + OFF_B3S);
        float m = -1e30f, wl[KMIX];
        #pragma unroll
        for (int k = 0; k < KMIX; k++) { wl[k] = pr[32 + k] + b3s[32 + k]; m = fmaxf(m, wl[k]); }
        float se = 0.f, es[KMIX];
        #pragma unroll
        for (int k = 0; k < KMIX; k++) { es[k] = __expf(wl[k] - m); se += es[k]; }
        float inv_se = 1.f / se;
        float y = 0.f, dsum = 0.f;
        #pragma unroll
        for (int k = 0; k < KMIX; k++) {
            float lsc = pr[k] + b3s[k];
            float shf = pr[16 + k] + b3s[16 + k];
            float wgt = fmaf(es[k] * inv_se, 0.84f, 0.01f);
            float alpha = __expf(lsc);
            float xx = alpha * (lgt + shf);
            float gg = 1.f / (1.f + __expf(-xx));
            y = fmaf(wgt, gg, y);
            dsum = fmaf(wgt * alpha, gg * (1.f - gg), dsum);
        }
        float dy_du = dsum / (sv * (1.f - sv)) * dsdu;
        ldj = logf(dy_du);
        int idx = 3 * (chnk * MCTA + tid) + off;
        g_z[bat * LLEN + idx] = mod2pi(fmaf(TWO_PI_F, y, zr));
        #pragma unroll
        for (int o = 16; o; o >>= 1) ldj += __shfl_down_sync(0xffffffff, ldj, o);
        if (lane == 0) *(float*)(gb + OFF_LDJP + wp * 4) = ldj;
    }
    __syncthreads();
    if (tid == 0) {
        float s = 0.f;
        #pragma unroll
        for (int i = 0; i < 2; i++) s += *(const float*)(gb + OFF_LDJP + i * 4);
        g_part[t * GRID + blk] = s;
        __threadfence();
        *(volatile uint32_t*)&g_flag[t][blk] = 1u;
    }
}

__global__ void final_kernel(float* __restrict__ out, int out_size) {
    int i = blockIdx.x * blockDim.x + threadIdx.x;
    if (i < BATCH * LLEN && i < out_size) out[i] = g_z[i];
    if (blockIdx.x == 0 && threadIdx.x < BATCH) {
        int o = BATCH * LLEN + threadIdx.x;
        if (o < out_size) {
            float s = 0.f;
            for (int t = 0; t < NT; t++)
                for (int c = 0; c < 16; c++)
                    s += g_part[t * GRID + threadIdx.x * 16 + c];
            out[o] = s;
        }
    }
}

extern "C" void kernel_launch(void* const* d_in, const int* in_sizes, int n_in,
                              void* d_out, int out_size) {
    const float* z  = (const float*)d_in[0];
    const float* W1 = (const float*)d_in[1];
    const float* b1 = (const float*)d_in[2];
    const float* W2 = (const float*)d_in[3];
    const float* b2 = (const float*)d_in[4];
    const float* W3 = (const float*)d_in[5];
    const float* b3 = (const float*)d_in[6];
    float* out = (float*)d_out;

    static int attr_set = 0;
    if (!attr_set) {
        cudaFuncSetAttribute(step_kernel, cudaFuncAttributeMaxDynamicSharedMemorySize, SMEM_DYN);
        attr_set = 1;
    }

    prep_w2<<<(NT * 256 * 256 + 255) / 256, 256>>>(W2);
    prep_w3<<<(NT * 256 * 64 + 255) / 256, 256>>>(W3);
    init_kernel<<<(BATCH * LLEN + 255) / 256, 256>>>(z);

    const int off_tab[3] = {0, 2, 1};
    for (int t = 0; t < NT; t++) {
        cudaLaunchConfig_t cfg = {};
        cfg.gridDim = dim3(GRID, 1, 1);
        cfg.blockDim = dim3(THREADS, 1, 1);
        cfg.dynamicSmemBytes = SMEM_DYN;
        cfg.stream = 0;
        cudaLaunchAttribute at[1];
        at[0].id = cudaLaunchAttributeProgrammaticStreamSerialization;
        at[0].val.programmaticStreamSerializationAllowed = 1;
        cfg.attrs = at;
        cfg.numAttrs = (t > 0) ? 1 : 0;
        cudaLaunchKernelEx(&cfg, step_kernel, W1, b1, b2, b3, t, off_tab[t % 3]);
    }
    final_kernel<<<(BATCH * LLEN + 255) / 256, 256>>>(out, out_size);
}